// round 2
// baseline (speedup 1.0000x reference)
#include <cuda_runtime.h>

// Cascaded 1st-order highpass -> lowpass IIR (bandpass), B=128 rows, T=262144.
// Time axis split into chunks; each thread runs a 512-sample zero-state warm-up
// before its chunk (pole magnitudes ~0.91 -> residual ~1e-22, far below 1e-3).

static constexpr int CHUNK = 1024;
static constexpr int WARM  = 512;
static constexpr int BLOCK = 128;

__global__ __launch_bounds__(BLOCK)
void bandpass_kernel(const float* __restrict__ x,
                     const float* __restrict__ p_cf,
                     const float* __restrict__ p_bw,
                     const float* __restrict__ p_gain,
                     const int*   __restrict__ p_sr,
                     float* __restrict__ out,
                     int T, int chunks_per_row)
{
    const int tid   = blockIdx.x * BLOCK + threadIdx.x;
    const int row   = tid / chunks_per_row;
    const int chunk = tid - row * chunks_per_row;

    // ---- coefficients (scipy butter(1, Wn), bilinear transform) ----
    const float cf   = *p_cf;
    const float bw   = *p_bw;
    const float gain = *p_gain;
    const float nyq  = 0.5f * (float)(*p_sr);
    const float PI_  = 3.14159265358979323846f;

    const float Kh    = tanf(PI_ * ((cf - 0.5f * bw) / nyq) * 0.5f);
    const float invh  = 1.0f / (Kh + 1.0f);
    const float bh0   = invh;            // highpass b0
    const float bh1   = -invh;           // highpass b1
    const float nah1  = -((Kh - 1.0f) * invh);   // -a1 (so y1 = fma(nah1, y1p, u))

    const float Kl    = tanf(PI_ * ((cf + 0.5f * bw) / nyq) * 0.5f);
    const float invl  = 1.0f / (Kl + 1.0f);
    const float bl0   = Kl * invl;       // lowpass b0
    const float bl1   = bl0;             // lowpass b1
    const float nal1  = -((Kl - 1.0f) * invl);   // -a1

    const float* __restrict__ xr = x   + (size_t)row * T;
    float* __restrict__       orow = out + (size_t)row * T;

    const int s   = chunk * CHUNK;           // first sample this thread OWNS
    int tb        = s - WARM;                // warm-up start
    if (tb < 0) tb = 0;
    const int end = s + CHUNK;

    float xp = (tb > 0) ? xr[tb - 1] : 0.0f; // x[t-1] carry
    float y1 = 0.0f;                         // highpass state
    float y2 = 0.0f;                         // lowpass state

    // One filter step. Chain kept to a single dependent FMA per stage:
    //   u  = bh0*xc + bh1*xp            (off-chain)
    //   y1 = nah1*y1_prev + u           (4-cycle chain)
    //   v  = bl0*y1 + bl1*y1_prev
    //   y2 = nal1*y2_prev + v           (4-cycle chain)
    #define BP_STEP(XC, YO)                                   \
        {                                                     \
            float u_  = fmaf(bh0, (XC), bh1 * xp);            \
            float y1n = fmaf(nah1, y1, u_);                   \
            float v_  = fmaf(bl0, y1n, bl1 * y1);             \
            float y2n = fmaf(nal1, y2, v_);                   \
            xp = (XC); y1 = y1n; y2 = y2n; (YO) = y2n;        \
        }

    // Single fused loop over [tb, end); stores only once t >= s.
    // Prefetch next float4 one iteration ahead to overlap L2/DRAM latency.
    float4 v = *reinterpret_cast<const float4*>(xr + tb);
    for (int t = tb; t < end; t += 4) {
        float4 vn;
        if (t + 4 < end)
            vn = *reinterpret_cast<const float4*>(xr + t + 4);

        float4 o;
        BP_STEP(v.x, o.x);
        BP_STEP(v.y, o.y);
        BP_STEP(v.z, o.z);
        BP_STEP(v.w, o.w);

        if (t >= s) {
            float4 so;
            so.x = o.x * gain; so.y = o.y * gain;
            so.z = o.z * gain; so.w = o.w * gain;
            *reinterpret_cast<float4*>(orow + t) = so;
        }
        v = vn;
    }
    #undef BP_STEP
}

extern "C" void kernel_launch(void* const* d_in, const int* in_sizes, int n_in,
                              void* d_out, int out_size)
{
    const float* x      = (const float*)d_in[0];
    const float* cf     = (const float*)d_in[1];
    const float* bw     = (const float*)d_in[2];
    const float* gain   = (const float*)d_in[3];
    const int*   sr     = (const int*)  d_in[4];
    float*       out    = (float*)d_out;

    const int B = 128;
    const int T = in_sizes[0] / B;           // 262144
    const int chunks_per_row = T / CHUNK;    // 256
    const int total_threads  = B * chunks_per_row;  // 32768
    const int grid = (total_threads + BLOCK - 1) / BLOCK;

    bandpass_kernel<<<grid, BLOCK>>>(x, cf, bw, gain, sr, out, T, chunks_per_row);
}

// round 3
// speedup vs baseline: 1.2432x; 1.2432x over previous
#include <cuda_runtime.h>

// Cascaded 1st-order highpass -> lowpass IIR (bandpass), B=128 rows, T=262144.
// Time axis split into 256-sample chunks; each thread runs a 256-sample
// zero-state warm-up (pole ~0.906 -> residual ~1e-11, far below 1e-3 gate).
// 131072 threads total -> ~28 warps/SM to hide memory latency.

static constexpr int CHUNK = 256;
static constexpr int WARM  = 256;
static constexpr int BLOCK = 128;

__global__ __launch_bounds__(BLOCK)
void bandpass_kernel(const float* __restrict__ x,
                     const float* __restrict__ p_cf,
                     const float* __restrict__ p_bw,
                     const float* __restrict__ p_gain,
                     const int*   __restrict__ p_sr,
                     float* __restrict__ out,
                     int T, int chunks_per_row)
{
    const int tid   = blockIdx.x * BLOCK + threadIdx.x;
    const int row   = tid / chunks_per_row;
    const int chunk = tid - row * chunks_per_row;

    // ---- coefficients (scipy butter(1, Wn), bilinear transform) ----
    const float cf   = *p_cf;
    const float bw   = *p_bw;
    const float gain = *p_gain;
    const float nyq  = 0.5f * (float)(*p_sr);
    const float PI_  = 3.14159265358979323846f;

    const float Kh    = tanf(PI_ * ((cf - 0.5f * bw) / nyq) * 0.5f);
    const float invh  = 1.0f / (Kh + 1.0f);
    const float bh0   = invh;                    // highpass: b0 = -b1
    const float nah1  = -((Kh - 1.0f) * invh);   // -a1

    const float Kl    = tanf(PI_ * ((cf + 0.5f * bw) / nyq) * 0.5f);
    const float invl  = 1.0f / (Kl + 1.0f);
    const float bl0   = Kl * invl;               // lowpass: b0 = b1
    const float nal1  = -((Kl - 1.0f) * invl);   // -a1

    const float* __restrict__ xr   = x   + (size_t)row * T;
    float* __restrict__       orow = out + (size_t)row * T;

    const int s  = chunk * CHUNK;        // first sample this thread OWNS
    int tb       = s - WARM;             // warm-up start
    if (tb < 0) tb = 0;

    float xp = (tb > 0) ? xr[tb - 1] : 0.0f;  // x[t-1] carry
    float y1 = 0.0f;                          // highpass state
    float y2 = 0.0f;                          // lowpass state

    // One filter step; recurrence kept to one dependent FMA per stage:
    //   u   = bh0*(xc - xp)                 (off-chain)
    //   y1n = nah1*y1 + u                   (4-cycle chain)
    //   v   = bl0*(y1n + y1)
    //   y2n = nal1*y2 + v                   (4-cycle chain)
    #define BP_STEP(XC, YO)                                   \
        {                                                     \
            float u_  = bh0 * ((XC) - xp);                    \
            float y1n = fmaf(nah1, y1, u_);                   \
            float v_  = bl0 * (y1n + y1);                     \
            float y2n = fmaf(nal1, y2, v_);                   \
            xp = (XC); y1 = y1n; y2 = y2n; (YO) = y2n;        \
        }

    // ---- warm-up loop: no stores ----
    #pragma unroll 4
    for (int t = tb; t < s; t += 4) {
        float4 v = *reinterpret_cast<const float4*>(xr + t);
        float d;
        BP_STEP(v.x, d); BP_STEP(v.y, d); BP_STEP(v.z, d); BP_STEP(v.w, d);
        (void)d;
    }

    // ---- main loop: owned samples, vector stores ----
    #pragma unroll 4
    for (int t = s; t < s + CHUNK; t += 4) {
        float4 v = *reinterpret_cast<const float4*>(xr + t);
        float4 o;
        BP_STEP(v.x, o.x); BP_STEP(v.y, o.y); BP_STEP(v.z, o.z); BP_STEP(v.w, o.w);
        o.x *= gain; o.y *= gain; o.z *= gain; o.w *= gain;
        *reinterpret_cast<float4*>(orow + t) = o;
    }
    #undef BP_STEP
}

extern "C" void kernel_launch(void* const* d_in, const int* in_sizes, int n_in,
                              void* d_out, int out_size)
{
    const float* x    = (const float*)d_in[0];
    const float* cf   = (const float*)d_in[1];
    const float* bw   = (const float*)d_in[2];
    const float* gain = (const float*)d_in[3];
    const int*   sr   = (const int*)  d_in[4];
    float*       out  = (float*)d_out;

    const int B = 128;
    const int T = in_sizes[0] / B;               // 262144
    const int chunks_per_row = T / CHUNK;        // 1024
    const int total_threads  = B * chunks_per_row;  // 131072
    const int grid = (total_threads + BLOCK - 1) / BLOCK;

    bandpass_kernel<<<grid, BLOCK>>>(x, cf, bw, gain, sr, out, T, chunks_per_row);
}